// round 15
// baseline (speedup 1.0000x reference)
#include <cuda_runtime.h>

#define FULL 0xffffffffu
typedef unsigned long long u64;
constexpr int NW = 10;   // wires
constexpr int NL = 4;    // layers

// Layer-1 fused gate bases: G = RY(th) * RZ(phi) (om pushed into phase tables)
__device__ float4 g_rot[NW * 2];
// Layers 2-4 RY coefficients: (cos(th/2), sin(th/2))
__device__ float2 g_rycs[3 * NW];
// Phase tables Gamma_g (g=0..2), pair p=(amp>>1) stored TRANSPOSED at
// idx = ((p&15)<<5) | (p>>4). g_phA = (cr0,cr1 | -ci0,-ci1) as ulonglong2,
// g_phB = (ci0, ci1) as u64 — directly consumable by fma.rn.f32x2.
__device__ ulonglong2 g_phA[3 * 512];
__device__ u64 g_phB[3 * 512];

// ---------------------------------------------------------------------------
// Prep: gate matrices + composed diagonal phase tables. One block, 1024 thr.
// ---------------------------------------------------------------------------
__device__ __forceinline__ u64 h_pack(float x, float y) {
    u64 d;
    asm("mov.b64 %0, {%1, %2};" : "=l"(d) : "f"(x), "f"(y));
    return d;
}

__global__ void prep_kernel(const float* __restrict__ w) {
    __shared__ float s_ang[1024], s_co[1024], s_si[1024];
    int v = threadIdx.x;

    if (v < NL * NW) {
        int l = v / NW, wi = v % NW;
        float phi = w[v * 3 + 0], th = w[v * 3 + 1];
        float s, c;
        sincosf(0.5f * th, &s, &c);
        if (l == 0) {
            float sp, cp;  // e^{-i phi/2} = cp + i sp
            sincosf(-0.5f * phi, &sp, &cp);
            // G = RY(th) RZ(phi)
            g_rot[wi * 2 + 0] = make_float4(c * cp, c * sp, -s * cp, s * sp);
            g_rot[wi * 2 + 1] = make_float4(s * cp, s * sp, c * cp, -c * sp);
        } else {
            g_rycs[(l - 1) * NW + wi] = make_float2(c, s);
        }
    }

    for (int g = 0; g < 3; ++g) {
        __syncthreads();
        // delta1 (RZ(om) of layer g) pushed through ring r=g+1: tmp[pi(u)] = a1(u)
        float a1 = 0.0f;
#pragma unroll
        for (int wi = 0; wi < NW; ++wi) {
            float om = w[(g * NW + wi) * 3 + 2];
            a1 += (((v >> (9 - wi)) & 1) ? 0.5f : -0.5f) * om;
        }
        int u = v, r = g + 1;
#pragma unroll
        for (int wi = 0; wi < NW; ++wi) {
            int pc = 9 - wi, pt = 9 - ((wi + r) % NW);
            if ((u >> pc) & 1) u ^= (1 << pt);
        }
        s_ang[u] = a1;
        __syncthreads();
        // add delta2 (RZ(phi) of layer g+1)
        float a = s_ang[v];
#pragma unroll
        for (int wi = 0; wi < NW; ++wi) {
            float phi = w[((g + 1) * NW + wi) * 3 + 0];
            a += (((v >> (9 - wi)) & 1) ? 0.5f : -0.5f) * phi;
        }
        float si, co;
        sincosf(a, &si, &co);
        s_co[v] = co;
        s_si[v] = si;
        __syncthreads();
        if (v < 512) {
            int v0 = 2 * v, v1 = 2 * v + 1;
            int idx = ((v & 15) << 5) | (v >> 4);
            ulonglong2 A;
            A.x = h_pack(s_co[v0], s_co[v1]);
            A.y = h_pack(-s_si[v0], -s_si[v1]);
            g_phA[g * 512 + idx] = A;
            g_phB[g * 512 + idx] = h_pack(s_si[v0], s_si[v1]);
        }
    }
}

// ---------------------------------------------------------------------------
// Packed f32x2 helpers — state lives in aligned 64-bit register pairs.
// ---------------------------------------------------------------------------
__device__ __forceinline__ u64 ffma2(u64 a, u64 b, u64 c) {
    u64 d;
    asm("fma.rn.f32x2 %0, %1, %2, %3;" : "=l"(d) : "l"(a), "l"(b), "l"(c));
    return d;
}
__device__ __forceinline__ u64 fmul2(u64 a, u64 b) {
    u64 d;
    asm("mul.rn.f32x2 %0, %1, %2;" : "=l"(d) : "l"(a), "l"(b));
    return d;
}
__device__ __forceinline__ u64 pk2(float x, float y) {
    u64 d;
    asm("mov.b64 %0, {%1, %2};" : "=l"(d) : "f"(x), "f"(y));
    return d;
}
__device__ __forceinline__ u64 pk(float v) { return pk2(v, v); }
__device__ __forceinline__ float2 unpk(u64 a) {
    float2 r;
    asm("mov.b64 {%0, %1}, %2;" : "=f"(r.x), "=f"(r.y) : "l"(a));
    return r;
}
__device__ __forceinline__ u64 swp64(u64 a) {
    float2 t = unpk(a);
    return pk2(t.y, t.x);
}
__device__ __forceinline__ u64 shx64(u64 v, int mask) {
    float2 t = unpk(v);
    t.x = __shfl_xor_sync(FULL, t.x, mask);
    t.y = __shfl_xor_sync(FULL, t.y, mask);
    return pk2(t.x, t.y);
}
__device__ __forceinline__ u64 shidx64(u64 v, int src) {
    float2 t = unpk(v);
    t.x = __shfl_sync(FULL, t.x, src);
    t.y = __shfl_sync(FULL, t.y, src);
    return pk2(t.x, t.y);
}
__device__ __forceinline__ float2 cmulf(float2 a, float2 b) {
    return make_float2(a.x * b.x - a.y * b.y, a.x * b.y + a.y * b.x);
}

// ---------------------------------------------------------------------------
// Layout: amplitude index bit for wire W is p = 9 - W.
//   bits 9..5 -> lane bits, bits 4..1 -> register index, bit 0 -> packed half
// ---------------------------------------------------------------------------

// Column 0 of fused layer-1 gate F = [RY(th)RZ(phi)] * RY(x*pi/2) for wire W.
__device__ __forceinline__ void colF(int W, float myc, float mys,
                                     float2& F00, float2& F10) {
    float cw = __shfl_sync(FULL, myc, W);
    float sw = __shfl_sync(FULL, mys, W);
    float4 g0 = g_rot[W * 2 + 0];
    float4 g1 = g_rot[W * 2 + 1];
    F00 = make_float2(fmaf(g0.x, cw, g0.z * sw), fmaf(g0.y, cw, g0.w * sw));
    F10 = make_float2(fmaf(g1.x, cw, g1.z * sw), fmaf(g1.y, cw, g1.w * sw));
}

// Build the post-layer-1 product state directly:
// amp(v) = prod_w (v_w ? F10_w : F00_w) applied to |0...0>.
__device__ __forceinline__ void buildInit(u64 RE[16], u64 IM[16], int lane,
                                          float myc, float mys) {
    float2 F00, F10;
    colF(0, myc, mys, F00, F10);
    float2 L = ((lane >> 4) & 1) ? F10 : F00;
#pragma unroll
    for (int W = 1; W < 5; ++W) {
        colF(W, myc, mys, F00, F10);
        float2 pick = ((lane >> (4 - W)) & 1) ? F10 : F00;
        L = cmulf(L, pick);
    }
    colF(9, myc, mys, F00, F10);
    float2 a0 = cmulf(L, F00), a1 = cmulf(L, F10);
    RE[0] = pk2(a0.x, a1.x);
    IM[0] = pk2(a0.y, a1.y);
    // Doubling tree: wire 8 -> reg bit 0, 7 -> 1, 6 -> 2, 5 -> 3
#pragma unroll
    for (int W = 8; W >= 5; --W) {
        colF(W, myc, mys, F00, F10);
        const int kb = 1 << (8 - W);
        const u64 c00 = pk(F00.x), s00 = pk(F00.y), n00 = pk(-F00.y);
        const u64 c10 = pk(F10.x), s10 = pk(F10.y), n10 = pk(-F10.y);
#pragma unroll
        for (int k = 0; k < 16; ++k) {
            if (k < kb) {
                u64 r = RE[k], i = IM[k];
                RE[k | kb] = ffma2(c10, r, fmul2(n10, i));
                IM[k | kb] = ffma2(c10, i, fmul2(s10, r));
                RE[k] = ffma2(c00, r, fmul2(n00, i));
                IM[k] = ffma2(c00, i, fmul2(s00, r));
            }
        }
    }
}

// Real RY on wire W: 4 f2-ops per register
template <int W>
__device__ __forceinline__ void ryGate(u64 RE[16], u64 IM[16], int lane, float c, float s) {
    constexpr int p = 9 - W;
    if constexpr (p >= 5) {
        constexpr int lb = p - 5;
        int bit = (lane >> lb) & 1;
        float sg = bit ? s : -s;
        const u64 cp = pk(c), sp = pk(sg);
#pragma unroll
        for (int k = 0; k < 16; ++k) {
            u64 ore = shx64(RE[k], 1 << lb);
            u64 oim = shx64(IM[k], 1 << lb);
            RE[k] = ffma2(cp, RE[k], fmul2(sp, ore));
            IM[k] = ffma2(cp, IM[k], fmul2(sp, oim));
        }
    } else if constexpr (p >= 1) {
        constexpr int kb = 1 << (p - 1);
        const u64 cp = pk(c), sp = pk(s), np = pk(-s);
#pragma unroll
        for (int k = 0; k < 16; ++k) {
            if (!(k & kb)) {
                const int j = k | kb;
                u64 a0re = RE[k], a0im = IM[k], a1re = RE[j], a1im = IM[j];
                RE[k] = ffma2(cp, a0re, fmul2(np, a1re));
                IM[k] = ffma2(cp, a0im, fmul2(np, a1im));
                RE[j] = ffma2(cp, a1re, fmul2(sp, a0re));
                IM[j] = ffma2(cp, a1im, fmul2(sp, a0im));
            }
        }
    } else {
        // p == 0: half-swap butterfly
        const u64 cp = pk(c), ss = pk2(-s, s);
#pragma unroll
        for (int k = 0; k < 16; ++k) {
            RE[k] = ffma2(cp, RE[k], fmul2(ss, swp64(RE[k])));
            IM[k] = ffma2(cp, IM[k], fmul2(ss, swp64(IM[k])));
        }
    }
}

// Gamma (composed diagonal): table loads feed FFMA2 directly (no repack)
__device__ __forceinline__ void applyPhase(u64 RE[16], u64 IM[16], int lane, int g) {
    const ulonglong2* __restrict__ A = g_phA + g * 512 + lane;
    const u64* __restrict__ Bv = g_phB + g * 512 + lane;
#pragma unroll
    for (int k = 0; k < 16; ++k) {
        ulonglong2 a = A[k << 5];     // a.x = (cr), a.y = (-ci)
        u64 ci = Bv[k << 5];
        u64 nre = ffma2(a.x, RE[k], fmul2(a.y, IM[k]));
        u64 nim = ffma2(a.x, IM[k], fmul2(ci, RE[k]));
        RE[k] = nre; IM[k] = nim;
    }
}

// ---------------------------------------------------------------------------
// CNOT cases
// ---------------------------------------------------------------------------
template <int CW, int TW>
__device__ __forceinline__ void cnotGate(u64 RE[16], u64 IM[16], int lane) {
    constexpr int pc = 9 - CW, pt = 9 - TW;
    if constexpr (pc >= 1 && pc <= 4 && pt >= 1 && pt <= 4) {
        constexpr int cm = 1 << (pc - 1), tm = 1 << (pt - 1);
#pragma unroll
        for (int k = 0; k < 16; ++k) {
            if ((k & cm) && !(k & tm)) {
                u64 a = RE[k]; RE[k] = RE[k | tm]; RE[k | tm] = a;
                u64 b = IM[k]; IM[k] = IM[k | tm]; IM[k | tm] = b;
            }
        }
    } else if constexpr (pc >= 1 && pc <= 4 && pt >= 5) {
        constexpr int cm = 1 << (pc - 1), tlm = 1 << (pt - 5);
#pragma unroll
        for (int k = 0; k < 16; ++k) {
            if (k & cm) { RE[k] = shx64(RE[k], tlm); IM[k] = shx64(IM[k], tlm); }
        }
    } else if constexpr (pc >= 1 && pc <= 4 && pt == 0) {
        constexpr int cm = 1 << (pc - 1);
#pragma unroll
        for (int k = 0; k < 16; ++k) {
            if (k & cm) { RE[k] = swp64(RE[k]); IM[k] = swp64(IM[k]); }
        }
    } else if constexpr (pc >= 5 && pt >= 1 && pt <= 4) {
        constexpr int tm = 1 << (pt - 1);
        bool c1 = (lane >> (pc - 5)) & 1;
#pragma unroll
        for (int k = 0; k < 16; ++k) {
            if (!(k & tm)) {
                u64 a = RE[k], b = RE[k | tm];
                RE[k] = c1 ? b : a; RE[k | tm] = c1 ? a : b;
                u64 e = IM[k], f = IM[k | tm];
                IM[k] = c1 ? f : e; IM[k | tm] = c1 ? e : f;
            }
        }
    } else if constexpr (pc >= 5 && pt == 0) {
        bool c1 = (lane >> (pc - 5)) & 1;
#pragma unroll
        for (int k = 0; k < 16; ++k) {
            u64 a = RE[k], b = IM[k];
            RE[k] = c1 ? swp64(a) : a;
            IM[k] = c1 ? swp64(b) : b;
        }
    } else if constexpr (pc == 0 && pt >= 5) {
        constexpr int tlm = 1 << (pt - 5);
#pragma unroll
        for (int k = 0; k < 16; ++k) {
            float2 r = unpk(RE[k]);
            r.y = __shfl_xor_sync(FULL, r.y, tlm);
            RE[k] = pk2(r.x, r.y);
            float2 i = unpk(IM[k]);
            i.y = __shfl_xor_sync(FULL, i.y, tlm);
            IM[k] = pk2(i.x, i.y);
        }
    } else if constexpr (pc == 0 && pt >= 1 && pt <= 4) {
        constexpr int tm = 1 << (pt - 1);
#pragma unroll
        for (int k = 0; k < 16; ++k) {
            if (!(k & tm)) {
                float2 rA = unpk(RE[k]), rB = unpk(RE[k | tm]);
                float t = rA.y; rA.y = rB.y; rB.y = t;
                RE[k] = pk2(rA.x, rA.y); RE[k | tm] = pk2(rB.x, rB.y);
                float2 iA = unpk(IM[k]), iB = unpk(IM[k | tm]);
                float u = iA.y; iA.y = iB.y; iB.y = u;
                IM[k] = pk2(iA.x, iA.y); IM[k | tm] = pk2(iB.x, iB.y);
            }
        }
    } else {
        constexpr int tlm = 1 << (pt - 5);
        int src = ((lane >> (pc - 5)) & 1) ? (lane ^ tlm) : lane;
#pragma unroll
        for (int k = 0; k < 16; ++k) { RE[k] = shidx64(RE[k], src); IM[k] = shidx64(IM[k], src); }
    }
}

// ---------------------------------------------------------------------------
// Sequencers
// ---------------------------------------------------------------------------
template <int W>
__device__ __forceinline__ void rySeq(u64 RE[16], u64 IM[16], int lane,
                                      const float2* __restrict__ cs) {
    float2 p = cs[W];
    ryGate<W>(RE, IM, lane, p.x, p.y);
    if constexpr (W < NW - 1) rySeq<W + 1>(RE, IM, lane, cs);
}

template <int R, int W>
__device__ __forceinline__ void cnotRest(u64 RE[16], u64 IM[16], int lane) {
    cnotGate<W, (W + R) % NW>(RE, IM, lane);
    if constexpr (W < NW - 1) cnotRest<R, W + 1>(RE, IM, lane);
}

template <int R>
__device__ __forceinline__ void cnotLayer(u64 RE[16], u64 IM[16], int lane) {
    int src = lane;
#pragma unroll
    for (int w = 4 - R; w >= 0; --w) {
        int cb = 4 - w, tb = 4 - w - R;
        src ^= (((src >> cb) & 1) << tb);
    }
#pragma unroll
    for (int k = 0; k < 16; ++k) { RE[k] = shidx64(RE[k], src); IM[k] = shidx64(IM[k], src); }
    cnotRest<R, 5 - R>(RE, IM, lane);
}

// ---------------------------------------------------------------------------
// Main kernel — one warp per block (R14 desync win kept)
// ---------------------------------------------------------------------------
__global__ void __launch_bounds__(32, 16)
vqc_kernel(const float* __restrict__ X, const float* __restrict__ bias,
           float* __restrict__ out, int B) {
    int warp = blockIdx.x;
    int lane = threadIdx.x;
    if (warp >= B) return;

    float x = (lane < NW) ? X[warp * NW + lane] : 0.0f;
    float mys, myc;
    sincosf(x * 0.78539816339744831f, &mys, &myc);

    u64 RE[16], IM[16];

    // Layer 1 collapses to direct product-state construction
    buildInit(RE, IM, lane, myc, mys);
    cnotLayer<1>(RE, IM, lane);

    // Layer 2: Gamma_0 + full RY layer + ring 2
    applyPhase(RE, IM, lane, 0);
    rySeq<0>(RE, IM, lane, g_rycs + 0 * NW);
    cnotLayer<2>(RE, IM, lane);

    // Layer 3: Gamma_1 + full RY layer + ring 3
    applyPhase(RE, IM, lane, 1);
    rySeq<0>(RE, IM, lane, g_rycs + 1 * NW);
    cnotLayer<3>(RE, IM, lane);

    // Layer 4: Gamma_2 + only the RYs on wires {1,5,9} (they carry the
    // measured parity P = Z1 Z5 Z9 after ring-4 deferral; others commute).
    applyPhase(RE, IM, lane, 2);
    {
        const float2* cs = g_rycs + 2 * NW;
        float2 p1 = cs[1], p5 = cs[5], p9 = cs[9];
        ryGate<1>(RE, IM, lane, p1.x, p1.y);   // lane gate (amp bit 8)
        ryGate<5>(RE, IM, lane, p5.x, p5.y);   // local gate (amp bit 4)
        ryGate<9>(RE, IM, lane, p9.x, p9.y);   // half gate (amp bit 0)
    }

    // Z on wire 9 through deferred ring 4: parity mask half ^ k_bit3 ^ lane_bit3
    u64 accA = 0ull, accB = 0ull;   // packed (0.0f, 0.0f)
#pragma unroll
    for (int k = 0; k < 8; ++k)
        accA = ffma2(RE[k], RE[k], ffma2(IM[k], IM[k], accA));
#pragma unroll
    for (int k = 8; k < 16; ++k)
        accB = ffma2(RE[k], RE[k], ffma2(IM[k], IM[k], accB));
    float2 pA = unpk(accA), pB = unpk(accB);
    float z = (pA.x - pA.y) - (pB.x - pB.y);
    if ((lane >> 3) & 1) z = -z;
#pragma unroll
    for (int o = 16; o; o >>= 1) z += __shfl_xor_sync(FULL, z, o);
    if (lane == 0) out[warp] = z + bias[0];
}

// ---------------------------------------------------------------------------
extern "C" void kernel_launch(void* const* d_in, const int* in_sizes, int n_in,
                              void* d_out, int out_size) {
    const float* X = (const float*)d_in[0];
    const float* w = (const float*)d_in[1];
    const float* bias = (const float*)d_in[2];
    float* out = (float*)d_out;

    int B = in_sizes[0] / NW;

    prep_kernel<<<1, 1024>>>(w);

    vqc_kernel<<<B, 32>>>(X, bias, out, B);  // one warp per block
}